// round 14
// baseline (speedup 1.0000x reference)
#include <cuda_runtime.h>
#include <cstdint>
#include <cfloat>

#define BB 8
#define NN 8192
#define SS 1024
#define KK 32
#define CC 64
#define DD 128
#define EPSF 1e-5f

// output layout: new_xyz (8,1024,3), feature (8,128,1024), new_xyz, feature
#define OFF_F1  24576
#define OFF_NX2 1073152
#define OFF_F2  1097728

// mega-kernel block ranges (512 threads each)
#define FPS_B0   0
#define FEAT_B0  8
#define KNN_B0   136          // 512 knn blocks, 16 warps each
#define U_B0     648          // 32 u blocks
#define TOT_BLKS 680

// ---------------- scratch (device globals; no allocation) ----------------
__device__ float g_f[BB*NN*CC];                 // 16 MB: per-point features
__device__ int   g_fps[BB*SS];
__device__ int   g_knn[BB*SS*KK];
__device__ float g_u[BB*SS*DD];                 // per-query layer-1 bias term
__device__ int   g_progress[BB];                // fps steps completed per batch
__device__ int   g_featdone;                    // feat blocks completed
// prepped (bn-folded) weights
__device__ float g_c1s[CC*3], g_t1[CC];
__device__ float g_c2s[CC*CC], g_t2c[CC];
__device__ float g_W1s[CC*DD];   // [d][o] = lconv1_w[o][d]      * s1l[o]
__device__ float g_Wd [CC*DD];   // [d][o] = (W[o][64+d]-W[o][d])* s1l[o]
__device__ float g_t1l[DD];
__device__ float g_W2s[DD*DD];   // [e][o] = lconv2_w[o][e] * s2l[o]
__device__ float g_t2l[DD];

// ---------------- packed f32x2 helpers (per-lane rn == scalar rn) ----------------
__device__ __forceinline__ unsigned long long pk2(float a, float b) {
    unsigned long long r; asm("mov.b64 %0, {%1,%2};" : "=l"(r) : "f"(a), "f"(b)); return r;
}
__device__ __forceinline__ void upk2(unsigned long long v, float& a, float& b) {
    asm("mov.b64 {%0,%1}, %2;" : "=f"(a), "=f"(b) : "l"(v));
}
__device__ __forceinline__ unsigned long long add2(unsigned long long a, unsigned long long b) {
    unsigned long long r; asm("add.rn.f32x2 %0, %1, %2;" : "=l"(r) : "l"(a), "l"(b)); return r;
}
__device__ __forceinline__ unsigned long long mul2(unsigned long long a, unsigned long long b) {
    unsigned long long r; asm("mul.rn.f32x2 %0, %1, %2;" : "=l"(r) : "l"(a), "l"(b)); return r;
}
__device__ __forceinline__ void st_release(int* p, int v) {
    asm volatile("st.release.gpu.b32 [%0], %1;" :: "l"(p), "r"(v) : "memory");
}
__device__ __forceinline__ int ld_acquire(const int* p) {
    int v; asm volatile("ld.acquire.gpu.b32 %0, [%1];" : "=r"(v) : "l"(p) : "memory"); return v;
}

// ---------------- prep: fold BN into weights + reset sync state ----------------
__global__ void prep_kernel(
    const float* __restrict__ c1w, const float* __restrict__ c2w,
    const float* __restrict__ l1w, const float* __restrict__ l2w,
    const float* __restrict__ b1g, const float* __restrict__ b1b, const float* __restrict__ b1m, const float* __restrict__ b1v,
    const float* __restrict__ b2g, const float* __restrict__ b2b, const float* __restrict__ b2m, const float* __restrict__ b2v,
    const float* __restrict__ g1g, const float* __restrict__ g1b, const float* __restrict__ g1m, const float* __restrict__ g1v,
    const float* __restrict__ g2g, const float* __restrict__ g2b, const float* __restrict__ g2m, const float* __restrict__ g2v)
{
    int t = blockIdx.x * blockDim.x + threadIdx.x;
    int st = gridDim.x * blockDim.x;
    if (t < BB) g_progress[t] = 0;
    if (t == 0) g_featdone = 0;
    for (int i = t; i < CC*3; i += st) { int e = i/3; float s = b1g[e]*rsqrtf(b1v[e]+EPSF); g_c1s[i] = c1w[i]*s; }
    for (int e = t; e < CC; e += st)  { float s = b1g[e]*rsqrtf(b1v[e]+EPSF); g_t1[e] = b1b[e]-b1m[e]*s; }
    for (int i = t; i < CC*CC; i += st){ int f = i/CC; float s = b2g[f]*rsqrtf(b2v[f]+EPSF); g_c2s[i] = c2w[i]*s; }
    for (int f = t; f < CC; f += st)  { float s = b2g[f]*rsqrtf(b2v[f]+EPSF); g_t2c[f] = b2b[f]-b2m[f]*s; }
    for (int i = t; i < CC*DD; i += st){
        int d = i / DD, o = i % DD;
        float s = g1g[o]*rsqrtf(g1v[o]+EPSF);
        g_W1s[i] = l1w[o*DD + d]*s;
        g_Wd [i] = (l1w[o*DD + CC + d] - l1w[o*DD + d])*s;
    }
    for (int o = t; o < DD; o += st) { float s = g1g[o]*rsqrtf(g1v[o]+EPSF); g_t1l[o] = g1b[o]-g1m[o]*s; }
    for (int i = t; i < DD*DD; i += st){
        int e = i / DD, o = i % DD;
        float s = g2g[o]*rsqrtf(g2v[o]+EPSF);
        g_W2s[i] = l2w[o*DD + e]*s;
    }
    for (int o = t; o < DD; o += st) { float s = g2g[o]*rsqrtf(g2v[o]+EPSF); g_t2l[o] = g2b[o]-g2m[o]*s; }
}

// ---------------- MEGA: fps(0..7) + feat(8..135) + knn(136..647, spin) + u(648..679, spin) ----------------
__global__ void __launch_bounds__(512) mega_kernel(const float* __restrict__ x, float* __restrict__ out)
{
    int tid = threadIdx.x;
    int bid = blockIdx.x;

    if (bid < FEAT_B0) {
        // ---------------- FPS path (R11 512-thread version + progress publish) ----------------
        __shared__ unsigned int pd[2][16];
        __shared__ unsigned int pi[2][16];
        int b = bid;
        int lane = tid & 31, wid = tid >> 5;
        const float* xb = x + (size_t)b * NN * 3;

        float rd[16];
        unsigned long long rx2[8], ry2[8], rz2[8];
#pragma unroll
        for (int jp = 0; jp < 8; jp++) {
            int i0 = tid + (2*jp)*512, i1 = i0 + 512;
            float ax = xb[i0*3], ay = xb[i0*3+1], az = xb[i0*3+2];
            float bx_ = xb[i1*3], by_ = xb[i1*3+1], bz_ = xb[i1*3+2];
            rx2[jp] = pk2(ax, bx_); ry2[jp] = pk2(ay, by_); rz2[jp] = pk2(az, bz_);
            rd[2*jp] = 1e10f; rd[2*jp+1] = 1e10f;
        }
        float cx = __ldg(xb), cy = __ldg(xb+1), cz = __ldg(xb+2);
        int far = 0;

        for (int t = 0; t < SS; t++) {
            if (tid == 0) {
                g_fps[b*SS + t] = far;
                int o1 = (b*SS + t) * 3;
                out[o1] = cx; out[o1+1] = cy; out[o1+2] = cz;
                out[OFF_NX2+o1] = cx; out[OFF_NX2+o1+1] = cy; out[OFF_NX2+o1+2] = cz;
                st_release(&g_progress[b], t + 1);   // orders g_fps write before progress
            }
            unsigned long long nx = pk2(-cx, -cx), ny = pk2(-cy, -cy), nz = pk2(-cz, -cz);
            // per lane: fadd(fadd(fmul(dx,dx),fmul(dy,dy)),fmul(dz,dz)) in rn — reference rounding
#pragma unroll
            for (int jp = 0; jp < 8; jp++) {
                unsigned long long dx = add2(rx2[jp], nx);
                unsigned long long dy = add2(ry2[jp], ny);
                unsigned long long dz = add2(rz2[jp], nz);
                unsigned long long s  = add2(add2(mul2(dx,dx), mul2(dy,dy)), mul2(dz,dz));
                float s0, s1; upk2(s, s0, s1);
                rd[2*jp]   = fminf(rd[2*jp],   s0);
                rd[2*jp+1] = fminf(rd[2*jp+1], s1);
            }
            // thread-local argmax: max value, then FIRST j (ascending j == ascending global idx)
            float m = rd[0];
#pragma unroll
            for (int j = 1; j < 16; j++) m = fmaxf(m, rd[j]);
            int j0 = 15;
#pragma unroll
            for (int j = 14; j >= 0; j--) if (rd[j] == m) j0 = j;
            unsigned int mb  = __float_as_uint(m);
            unsigned int inv = (unsigned)(NN-1 - (tid + j0*512));
            unsigned int wmax = __reduce_max_sync(0xffffffffu, mb);
            unsigned int winv = __reduce_max_sync(0xffffffffu, (mb == wmax) ? inv : 0u);
            if (lane == 0) { pd[t & 1][wid] = wmax; pi[t & 1][wid] = winv; }
            __syncthreads();
            unsigned int d2 = pd[t & 1][lane & 15];
            unsigned int i2 = pi[t & 1][lane & 15];
            unsigned int gmax = __reduce_max_sync(0xffffffffu, d2);
            unsigned int ginv = __reduce_max_sync(0xffffffffu, (d2 == gmax) ? i2 : 0u);
            far = NN-1 - (int)ginv;
            cx = __ldg(xb + far*3); cy = __ldg(xb + far*3 + 1); cz = __ldg(xb + far*3 + 2);
        }
    } else if (bid < KNN_B0) {
        // ---------------- feat path ----------------
        __shared__ float sc1[CC*3], st1[CC], st2[CC];
        __shared__ float4 sc2[CC*16];
        for (int i = tid; i < CC*3; i += 512) sc1[i] = g_c1s[i];
        for (int i = tid; i < CC; i += 512) { st1[i] = g_t1[i]; st2[i] = g_t2c[i]; }
        for (int i = tid; i < CC*16; i += 512) sc2[i] = ((const float4*)g_c2s)[i];
        __syncthreads();

        int p = (bid - FEAT_B0) * 512 + tid;              // 0..65535
        float x0 = x[p*3], x1 = x[p*3+1], x2 = x[p*3+2];
        float h[CC];
#pragma unroll
        for (int e = 0; e < CC; e++)
            h[e] = fmaxf(fmaf(x2, sc1[e*3+2], fmaf(x1, sc1[e*3+1], x0*sc1[e*3])) + st1[e], 0.f);

        float* outf = g_f + (size_t)p * CC;
        for (int o = 0; o < CC; o++) {
            float a0=0.f, a1=0.f, a2=0.f, a3=0.f;
#pragma unroll
            for (int e4 = 0; e4 < 16; e4++) {
                float4 w = sc2[o*16 + e4];
                a0 = fmaf(h[e4*4+0], w.x, a0);
                a1 = fmaf(h[e4*4+1], w.y, a1);
                a2 = fmaf(h[e4*4+2], w.z, a2);
                a3 = fmaf(h[e4*4+3], w.w, a3);
            }
            outf[o] = fmaxf((a0+a1)+(a2+a3) + st2[o], 0.f);
        }
        __syncthreads();
        if (tid == 0) { __threadfence(); atomicAdd(&g_featdone, 1); }
    } else if (bid < U_B0) {
        // ---------------- KNN path: 16 warps = 16 queries; spin on fps progress ----------------
        __shared__ float px[512], py[512], pz[512];
        __shared__ int ready;
        int lane = tid & 31, wid = tid >> 5;
        int qb = (bid - KNN_B0) * 16;          // first query of this block
        int b = qb >> 10;
        int need = (qb & 1023) + 16;           // need fps steps [0, qb%1024+15] done
        if (tid == 0) {
            while (ld_acquire(&g_progress[b]) < need) __nanosleep(128);
            ready = 1;
        }
        __syncthreads();
        (void)ready;

        int sg = qb + wid;
        const float* xb = x + (size_t)b * NN * 3;
        int nq = g_fps[sg];
        float qx = xb[nq*3], qy = xb[nq*3+1], qz = xb[nq*3+2];

        unsigned long long cur = 0xFFFFFFFFFFFFFFFFull;
        unsigned long long worst = 0xFFFFFFFFFFFFFFFFull;

        for (int base = 0; base < NN; base += 512) {
            __syncthreads();
            for (int i = tid; i < 512; i += 512) {
                int n = base + i;
                px[i] = xb[n*3]; py[i] = xb[n*3+1]; pz[i] = xb[n*3+2];
            }
            __syncthreads();
#pragma unroll 4
            for (int s = 0; s < 512; s += 32) {
                int i = s + lane;
                float dx = qx - px[i], dy = qy - py[i], dz = qz - pz[i];
                float d = fmaf(dz, dz, fmaf(dy, dy, dx*dx));
                unsigned long long cand =
                    ((unsigned long long)__float_as_uint(d) << 32) | (unsigned)(base + i);
                unsigned int ball = __ballot_sync(0xffffffffu, cand < worst);
                while (ball) {                  // warp-uniform loop
                    int src = __ffs(ball) - 1; ball &= ball - 1;
                    unsigned long long ck = __shfl_sync(0xffffffffu, cand, src);
                    if (ck < worst) {
                        unsigned int lt = __ballot_sync(0xffffffffu, cur < ck);
                        int pos = __popc(lt);
                        unsigned long long up = __shfl_up_sync(0xffffffffu, cur, 1);
                        if (lane > pos) cur = up;
                        if (lane == pos) cur = ck;
                        worst = __shfl_sync(0xffffffffu, cur, 31);
                    }
                }
            }
        }
        g_knn[(size_t)sg*KK + lane] = (int)(unsigned)(cur & 0xffffffffu);
    } else {
        // ---------------- u path: 4 queries in parallel; spin on fps range + feat done ----------------
        __shared__ float sWd[CC*DD];   // 32 KB, layout [d][o]
        __shared__ float st[DD];
        __shared__ float sc[4][CC];
        __shared__ int ready;
        int ub = bid - U_B0;                    // 0..31
        int batch = ub >> 2;
        int need = ((ub & 3) * 256) + 256;      // this block's queries span steps [(ub&3)*256, +255]
        int qg = tid >> 7, t128 = tid & 127;

        for (int i = tid; i < CC*DD; i += 512) sWd[i] = g_Wd[i];
        if (tid < DD) st[tid] = g_t1l[tid];
        if (tid == 0) {
            while (ld_acquire(&g_progress[batch]) < need) __nanosleep(256);
            while (ld_acquire(&g_featdone) < 128) __nanosleep(256);
            ready = 1;
        }
        __syncthreads();
        (void)ready;

        for (int it = 0; it < 64; it++) {
            int sg = ub * 256 + it * 4 + qg;    // batch*1024 + (ub&3)*256 + it*4 + qg
            __syncthreads();
            if (t128 < CC) {
                int n = g_fps[sg];
                sc[qg][t128] = g_f[((size_t)(batch*NN) + n)*CC + t128];
            }
            __syncthreads();
            float a0=0.f,a1=0.f,a2=0.f,a3=0.f;
#pragma unroll
            for (int d = 0; d < CC; d += 4) {
                a0 = fmaf(sc[qg][d+0], sWd[(d+0)*DD + t128], a0);
                a1 = fmaf(sc[qg][d+1], sWd[(d+1)*DD + t128], a1);
                a2 = fmaf(sc[qg][d+2], sWd[(d+2)*DD + t128], a2);
                a3 = fmaf(sc[qg][d+3], sWd[(d+3)*DD + t128], a3);
            }
            g_u[(size_t)sg*DD + t128] = (a0+a1)+(a2+a3) + st[t128];
        }
    }
}

// ---------------- K3: fused layer1 + layer2 + k-max (unchanged from R13) ----------------
__global__ void __launch_bounds__(128) l1l2_kernel(float* __restrict__ out)
{
    __shared__ float4 gs[KK*16];        // 8 KB: grouped rows of one query
    __shared__ float  hs[2][KK*DD];     // 32 KB: layer-1 activations, 2 queries
    __shared__ float  su[2*DD];
    __shared__ int    kn[2*KK];
    int tid = threadIdx.x;
    int sg0 = blockIdx.x * 2;
    int b = sg0 >> 10, s0 = sg0 & (SS-1);

    su[tid]       = g_u[(size_t)sg0*DD + tid];
    su[tid + DD]  = g_u[(size_t)sg0*DD + tid + DD];
    if (tid < 2*KK) kn[tid] = g_knn[(size_t)sg0*KK + tid];

    float w1[CC];
#pragma unroll
    for (int d = 0; d < CC; d++) w1[d] = g_W1s[d*DD + tid];

    for (int q = 0; q < 2; q++) {
        __syncthreads();
#pragma unroll
        for (int j = 0; j < 4; j++) {
            int idx = tid + j*128;
            int r = idx >> 4, c = idx & 15;
            int n = kn[q*KK + r];
            gs[idx] = ((const float4*)(g_f + ((size_t)(b*NN) + n)*CC))[c];
        }
        __syncthreads();
        float uu = su[q*DD + tid];
        for (int k = 0; k < KK; k++) {
            float a0=0.f,a1=0.f,a2=0.f,a3=0.f;
#pragma unroll
            for (int d4 = 0; d4 < 16; d4++) {
                float4 g4 = gs[k*16 + d4];
                a0 = fmaf(g4.x, w1[d4*4+0], a0);
                a1 = fmaf(g4.y, w1[d4*4+1], a1);
                a2 = fmaf(g4.z, w1[d4*4+2], a2);
                a3 = fmaf(g4.w, w1[d4*4+3], a3);
            }
            hs[q][k*DD + tid] = fmaxf((a0+a1)+(a2+a3) + uu, 0.f);
        }
    }

    float w2[DD];
#pragma unroll
    for (int e = 0; e < DD; e++) w2[e] = g_W2s[e*DD + tid];
    float t2 = g_t2l[tid];
    __syncthreads();

    float m[2];
#pragma unroll
    for (int q = 0; q < 2; q++) {
        const float4* h4p = (const float4*)hs[q];
        float mm = -FLT_MAX;
        for (int k = 0; k < KK; k++) {
            float a0=0.f,a1=0.f,a2=0.f,a3=0.f;
#pragma unroll
            for (int e4 = 0; e4 < 32; e4++) {
                float4 h4 = h4p[k*32 + e4];
                a0 = fmaf(h4.x, w2[e4*4+0], a0);
                a1 = fmaf(h4.y, w2[e4*4+1], a1);
                a2 = fmaf(h4.z, w2[e4*4+2], a2);
                a3 = fmaf(h4.w, w2[e4*4+3], a3);
            }
            float acc = (a0+a1)+(a2+a3);
            mm = fmaxf(mm, acc);
        }
        m[q] = fmaxf(mm + t2, 0.f);    // max-then-(+t2,relu): monotone, identical result
    }
    size_t off = (size_t)b*(DD*SS) + (size_t)tid*SS + s0;
    float2 v; v.x = m[0]; v.y = m[1];
    *(float2*)(out + OFF_F1 + off) = v;
    *(float2*)(out + OFF_F2 + off) = v;
}

// ---------------- launch ----------------
extern "C" void kernel_launch(void* const* d_in, const int* in_sizes, int n_in,
                              void* d_out, int out_size)
{
    const float* x   = (const float*)d_in[0];
    const float* c1w = (const float*)d_in[1];
    const float* c2w = (const float*)d_in[2];
    const float* l1w = (const float*)d_in[3];
    const float* l2w = (const float*)d_in[4];
    const float* b1g = (const float*)d_in[5],  *b1b = (const float*)d_in[6],
               * b1m = (const float*)d_in[7],  *b1v = (const float*)d_in[8];
    const float* b2g = (const float*)d_in[9],  *b2b = (const float*)d_in[10],
               * b2m = (const float*)d_in[11], *b2v = (const float*)d_in[12];
    const float* g1g = (const float*)d_in[13], *g1b = (const float*)d_in[14],
               * g1m = (const float*)d_in[15], *g1v = (const float*)d_in[16];
    const float* g2g = (const float*)d_in[17], *g2b = (const float*)d_in[18],
               * g2m = (const float*)d_in[19], *g2v = (const float*)d_in[20];
    float* out = (float*)d_out;

    prep_kernel<<<64, 256>>>(c1w, c2w, l1w, l2w,
                             b1g, b1b, b1m, b1v, b2g, b2b, b2m, b2v,
                             g1g, g1b, g1m, g1v, g2g, g2b, g2m, g2v);
    mega_kernel<<<TOT_BLKS, 512>>>(x, out);
    l1l2_kernel<<<BB*SS/2, 128>>>(out);
}

// round 15
// speedup vs baseline: 1.1221x; 1.1221x over previous
#include <cuda_runtime.h>
#include <cstdint>
#include <cfloat>

#define BB 8
#define NN 8192
#define SS 1024
#define KK 32
#define CC 64
#define DD 128
#define EPSF 1e-5f

// output layout: new_xyz (8,1024,3), feature (8,128,1024), new_xyz, feature
#define OFF_F1  24576
#define OFF_NX2 1073152
#define OFF_F2  1097728

// ---------------- scratch (device globals; no allocation) ----------------
__device__ float g_f[BB*NN*CC];                 // 16 MB: per-point features
__device__ int   g_fps[BB*SS];
__device__ int   g_knn[BB*SS*KK];
__device__ float g_u[BB*SS*DD];                 // per-query layer-1 bias term
// prepped (bn-folded) weights
__device__ float g_c1s[CC*3], g_t1[CC];
__device__ float g_c2s[CC*CC], g_t2c[CC];
__device__ float g_W1s[CC*DD];   // [d][o] = lconv1_w[o][d]      * s1l[o]
__device__ float g_Wd [CC*DD];   // [d][o] = (W[o][64+d]-W[o][d])* s1l[o]
__device__ float g_t1l[DD];
__device__ float g_W2s[DD*DD];   // [e][o] = lconv2_w[o][e] * s2l[o]
__device__ float g_t2l[DD];

// ---------------- packed f32x2 helpers (per-lane rn == scalar rn) ----------------
__device__ __forceinline__ unsigned long long pk2(float a, float b) {
    unsigned long long r; asm("mov.b64 %0, {%1,%2};" : "=l"(r) : "f"(a), "f"(b)); return r;
}
__device__ __forceinline__ void upk2(unsigned long long v, float& a, float& b) {
    asm("mov.b64 {%0,%1}, %2;" : "=f"(a), "=f"(b) : "l"(v));
}
__device__ __forceinline__ unsigned long long add2(unsigned long long a, unsigned long long b) {
    unsigned long long r; asm("add.rn.f32x2 %0, %1, %2;" : "=l"(r) : "l"(a), "l"(b)); return r;
}
__device__ __forceinline__ unsigned long long mul2(unsigned long long a, unsigned long long b) {
    unsigned long long r; asm("mul.rn.f32x2 %0, %1, %2;" : "=l"(r) : "l"(a), "l"(b)); return r;
}

// ---------------- prep: fold BN into weights ----------------
__global__ void prep_kernel(
    const float* __restrict__ c1w, const float* __restrict__ c2w,
    const float* __restrict__ l1w, const float* __restrict__ l2w,
    const float* __restrict__ b1g, const float* __restrict__ b1b, const float* __restrict__ b1m, const float* __restrict__ b1v,
    const float* __restrict__ b2g, const float* __restrict__ b2b, const float* __restrict__ b2m, const float* __restrict__ b2v,
    const float* __restrict__ g1g, const float* __restrict__ g1b, const float* __restrict__ g1m, const float* __restrict__ g1v,
    const float* __restrict__ g2g, const float* __restrict__ g2b, const float* __restrict__ g2m, const float* __restrict__ g2v)
{
    int t = blockIdx.x * blockDim.x + threadIdx.x;
    int st = gridDim.x * blockDim.x;
    for (int i = t; i < CC*3; i += st) { int e = i/3; float s = b1g[e]*rsqrtf(b1v[e]+EPSF); g_c1s[i] = c1w[i]*s; }
    for (int e = t; e < CC; e += st)  { float s = b1g[e]*rsqrtf(b1v[e]+EPSF); g_t1[e] = b1b[e]-b1m[e]*s; }
    for (int i = t; i < CC*CC; i += st){ int f = i/CC; float s = b2g[f]*rsqrtf(b2v[f]+EPSF); g_c2s[i] = c2w[i]*s; }
    for (int f = t; f < CC; f += st)  { float s = b2g[f]*rsqrtf(b2v[f]+EPSF); g_t2c[f] = b2b[f]-b2m[f]*s; }
    for (int i = t; i < CC*DD; i += st){
        int d = i / DD, o = i % DD;
        float s = g1g[o]*rsqrtf(g1v[o]+EPSF);
        g_W1s[i] = l1w[o*DD + d]*s;
        g_Wd [i] = (l1w[o*DD + CC + d] - l1w[o*DD + d])*s;
    }
    for (int o = t; o < DD; o += st) { float s = g1g[o]*rsqrtf(g1v[o]+EPSF); g_t1l[o] = g1b[o]-g1m[o]*s; }
    for (int i = t; i < DD*DD; i += st){
        int e = i / DD, o = i % DD;
        float s = g2g[o]*rsqrtf(g2v[o]+EPSF);
        g_W2s[i] = l2w[o*DD + e]*s;
    }
    for (int o = t; o < DD; o += st) { float s = g2g[o]*rsqrtf(g2v[o]+EPSF); g_t2l[o] = g2b[o]-g2m[o]*s; }
}

// ---------------- K1: fused FPS (blocks 0..7) + feat (blocks 8..71), 1024 threads ----------------
__global__ void __launch_bounds__(1024) fps_feat_kernel(const float* __restrict__ x, float* __restrict__ out)
{
    int tid = threadIdx.x;
    if (blockIdx.x < BB) {
        // ---------------- FPS path ----------------
        __shared__ unsigned int pd[2][32];   // per-warp best dist bits
        __shared__ unsigned int pi[2][32];   // per-warp best inv index
        int b = blockIdx.x;
        int lane = tid & 31, wid = tid >> 5;
        const float* xb = x + (size_t)b * NN * 3;

        float rd[8];
        unsigned long long rx2[4], ry2[4], rz2[4];
#pragma unroll
        for (int jp = 0; jp < 4; jp++) {
            int i0 = tid + (2*jp)*1024, i1 = i0 + 1024;
            float ax = xb[i0*3], ay = xb[i0*3+1], az = xb[i0*3+2];
            float bx_ = xb[i1*3], by_ = xb[i1*3+1], bz_ = xb[i1*3+2];
            rx2[jp] = pk2(ax, bx_); ry2[jp] = pk2(ay, by_); rz2[jp] = pk2(az, bz_);
            rd[2*jp] = 1e10f; rd[2*jp+1] = 1e10f;
        }
        float cx = __ldg(xb), cy = __ldg(xb+1), cz = __ldg(xb+2);
        int far = 0;

        for (int t = 0; t < SS; t++) {
            if (tid == 0) {
                g_fps[b*SS + t] = far;
                int o1 = (b*SS + t) * 3;
                out[o1] = cx; out[o1+1] = cy; out[o1+2] = cz;
                out[OFF_NX2+o1] = cx; out[OFF_NX2+o1+1] = cy; out[OFF_NX2+o1+2] = cz;
            }
            unsigned long long nx = pk2(-cx, -cx), ny = pk2(-cy, -cy), nz = pk2(-cz, -cz);
            // per lane: fadd(fadd(fmul(dx,dx),fmul(dy,dy)),fmul(dz,dz)) in rn — reference rounding
#pragma unroll
            for (int jp = 0; jp < 4; jp++) {
                unsigned long long dx = add2(rx2[jp], nx);
                unsigned long long dy = add2(ry2[jp], ny);
                unsigned long long dz = add2(rz2[jp], nz);
                unsigned long long s  = add2(add2(mul2(dx,dx), mul2(dy,dy)), mul2(dz,dz));
                float s0, s1; upk2(s, s0, s1);
                rd[2*jp]   = fminf(rd[2*jp],   s0);
                rd[2*jp+1] = fminf(rd[2*jp+1], s1);
            }
            // thread-local argmax: max value, then FIRST j (ascending j == ascending global idx)
            float m = rd[0];
#pragma unroll
            for (int j = 1; j < 8; j++) m = fmaxf(m, rd[j]);
            int j0 = 7;
#pragma unroll
            for (int j = 6; j >= 0; j--) if (rd[j] == m) j0 = j;
            unsigned int mb  = __float_as_uint(m);
            unsigned int inv = (unsigned)(NN-1 - (tid + j0*1024));
            // warp reduce via REDUX: max dist bits, then max inv among tied lanes
            unsigned int wmax = __reduce_max_sync(0xffffffffu, mb);
            unsigned int winv = __reduce_max_sync(0xffffffffu, (mb == wmax) ? inv : 0u);
            if (lane == 0) { pd[t & 1][wid] = wmax; pi[t & 1][wid] = winv; }
            __syncthreads();
            // every warp redundantly reduces the 32 partials (double buffer -> no 2nd barrier)
            unsigned int d2 = pd[t & 1][lane];
            unsigned int i2 = pi[t & 1][lane];
            unsigned int gmax = __reduce_max_sync(0xffffffffu, d2);
            unsigned int ginv = __reduce_max_sync(0xffffffffu, (d2 == gmax) ? i2 : 0u);
            far = NN-1 - (int)ginv;
            cx = __ldg(xb + far*3); cy = __ldg(xb + far*3 + 1); cz = __ldg(xb + far*3 + 2);
        }
    } else {
        // ---------------- feat path ----------------
        __shared__ float sc1[CC*3], st1[CC], st2[CC];
        __shared__ float4 sc2[CC*16];
        for (int i = tid; i < CC*3; i += 1024) sc1[i] = g_c1s[i];
        for (int i = tid; i < CC; i += 1024) { st1[i] = g_t1[i]; st2[i] = g_t2c[i]; }
        for (int i = tid; i < CC*16; i += 1024) sc2[i] = ((const float4*)g_c2s)[i];
        __syncthreads();

        int p = (blockIdx.x - BB) * 1024 + tid;           // 0..65535
        float x0 = x[p*3], x1 = x[p*3+1], x2 = x[p*3+2];
        float h[CC];
#pragma unroll
        for (int e = 0; e < CC; e++)
            h[e] = fmaxf(fmaf(x2, sc1[e*3+2], fmaf(x1, sc1[e*3+1], x0*sc1[e*3])) + st1[e], 0.f);

        float* outf = g_f + (size_t)p * CC;
        for (int o = 0; o < CC; o++) {
            float a0=0.f, a1=0.f, a2=0.f, a3=0.f;
#pragma unroll
            for (int e4 = 0; e4 < 16; e4++) {
                float4 w = sc2[o*16 + e4];
                a0 = fmaf(h[e4*4+0], w.x, a0);
                a1 = fmaf(h[e4*4+1], w.y, a1);
                a2 = fmaf(h[e4*4+2], w.z, a2);
                a3 = fmaf(h[e4*4+3], w.w, a3);
            }
            outf[o] = fmaxf((a0+a1)+(a2+a3) + st2[o], 0.f);
        }
    }
}

// ---------------- K2: fused KNN (blocks 0..1023) + u (blocks 1024..1087), 256 threads ----------------
// knn: warp per query, register-sorted top-32, zero local memory (R13 version).
// u:   two independent 128-thread halves per block; per-half math identical to R13 u_kernel.
#define KNN_WPB 8      // warps (queries) per knn block
#define KNN_PTILE 512  // points staged in smem per tile
__global__ void __launch_bounds__(256) knn_u_kernel(const float* __restrict__ x)
{
    int tid = threadIdx.x;
    if (blockIdx.x < BB*SS/KNN_WPB) {
        // ---------------- KNN path ----------------
        __shared__ float px[KNN_PTILE], py[KNN_PTILE], pz[KNN_PTILE];
        int lane = tid & 31, wid = tid >> 5;
        int sg = blockIdx.x * KNN_WPB + wid;       // query id (block spans one batch)
        int b = sg >> 10;
        const float* xb = x + (size_t)b * NN * 3;
        int nq = g_fps[sg];
        float qx = xb[nq*3], qy = xb[nq*3+1], qz = xb[nq*3+2];

        unsigned long long cur = 0xFFFFFFFFFFFFFFFFull;
        unsigned long long worst = 0xFFFFFFFFFFFFFFFFull;

        for (int base = 0; base < NN; base += KNN_PTILE) {
            __syncthreads();
            for (int i = tid; i < KNN_PTILE; i += KNN_WPB*32) {
                int n = base + i;
                px[i] = xb[n*3]; py[i] = xb[n*3+1]; pz[i] = xb[n*3+2];
            }
            __syncthreads();
#pragma unroll 4
            for (int s = 0; s < KNN_PTILE; s += 32) {
                int i = s + lane;
                float dx = qx - px[i], dy = qy - py[i], dz = qz - pz[i];
                float d = fmaf(dz, dz, fmaf(dy, dy, dx*dx));
                unsigned long long cand =
                    ((unsigned long long)__float_as_uint(d) << 32) | (unsigned)(base + i);
                unsigned int ball = __ballot_sync(0xffffffffu, cand < worst);
                while (ball) {                      // warp-uniform loop (ballot is uniform)
                    int src = __ffs(ball) - 1; ball &= ball - 1;
                    unsigned long long ck = __shfl_sync(0xffffffffu, cand, src);
                    if (ck < worst) {               // uniform (ck, worst uniform)
                        unsigned int lt = __ballot_sync(0xffffffffu, cur < ck);
                        int pos = __popc(lt);       // insertion position (keys unique: idx in key)
                        unsigned long long up = __shfl_up_sync(0xffffffffu, cur, 1);
                        if (lane > pos) cur = up;   // shift tail; lane 31's (old worst) evicted
                        if (lane == pos) cur = ck;
                        worst = __shfl_sync(0xffffffffu, cur, 31);
                    }
                }
            }
        }
        // order within the 32 irrelevant downstream (max over k)
        g_knn[(size_t)sg*KK + lane] = (int)(unsigned)(cur & 0xffffffffu);
    } else {
        // ---------------- u path: u[s][o] = c·(Wb-Wa)'[o] + t1l[o], c = f[fps[s]] ----------------
        __shared__ float sWd[CC*DD];   // 32 KB, layout [d][o]
        __shared__ float st[DD];
        __shared__ float sc[2][CC];
        int ub = blockIdx.x - BB*SS/KNN_WPB;        // 0..63
        int half = tid >> 7, t128 = tid & 127;      // two independent 128-thread halves
        for (int i = tid; i < CC*DD; i += 256) sWd[i] = g_Wd[i];
        if (tid < DD) st[tid] = g_t1l[tid];
        for (int q = 0; q < 64; q++) {
            int sg = (ub*2 + half) * 64 + q;        // halves cover 128 consecutive query groups
            __syncthreads();
            if (t128 < CC) {
                int b = sg / SS;
                int n = g_fps[sg];
                sc[half][t128] = g_f[((size_t)(b*NN) + n)*CC + t128];
            }
            __syncthreads();
            float a0=0.f,a1=0.f,a2=0.f,a3=0.f;
#pragma unroll
            for (int d = 0; d < CC; d += 4) {
                a0 = fmaf(sc[half][d+0], sWd[(d+0)*DD + t128], a0);
                a1 = fmaf(sc[half][d+1], sWd[(d+1)*DD + t128], a1);
                a2 = fmaf(sc[half][d+2], sWd[(d+2)*DD + t128], a2);
                a3 = fmaf(sc[half][d+3], sWd[(d+3)*DD + t128], a3);
            }
            g_u[(size_t)sg*DD + t128] = (a0+a1)+(a2+a3) + st[t128];
        }
    }
}

// ---------------- K3: fused layer1 + layer2 + k-max (unchanged from R13) ----------------
__global__ void __launch_bounds__(128) l1l2_kernel(float* __restrict__ out)
{
    __shared__ float4 gs[KK*16];        // 8 KB: grouped rows of one query
    __shared__ float  hs[2][KK*DD];     // 32 KB: layer-1 activations, 2 queries
    __shared__ float  su[2*DD];
    __shared__ int    kn[2*KK];
    int tid = threadIdx.x;
    int sg0 = blockIdx.x * 2;
    int b = sg0 >> 10, s0 = sg0 & (SS-1);

    su[tid]       = g_u[(size_t)sg0*DD + tid];
    su[tid + DD]  = g_u[(size_t)sg0*DD + tid + DD];
    if (tid < 2*KK) kn[tid] = g_knn[(size_t)sg0*KK + tid];

    float w1[CC];
#pragma unroll
    for (int d = 0; d < CC; d++) w1[d] = g_W1s[d*DD + tid];

    for (int q = 0; q < 2; q++) {
        __syncthreads();
#pragma unroll
        for (int j = 0; j < 4; j++) {
            int idx = tid + j*128;
            int r = idx >> 4, c = idx & 15;
            int n = kn[q*KK + r];
            gs[idx] = ((const float4*)(g_f + ((size_t)(b*NN) + n)*CC))[c];
        }
        __syncthreads();
        float uu = su[q*DD + tid];
        for (int k = 0; k < KK; k++) {
            float a0=0.f,a1=0.f,a2=0.f,a3=0.f;
#pragma unroll
            for (int d4 = 0; d4 < 16; d4++) {
                float4 g4 = gs[k*16 + d4];
                a0 = fmaf(g4.x, w1[d4*4+0], a0);
                a1 = fmaf(g4.y, w1[d4*4+1], a1);
                a2 = fmaf(g4.z, w1[d4*4+2], a2);
                a3 = fmaf(g4.w, w1[d4*4+3], a3);
            }
            hs[q][k*DD + tid] = fmaxf((a0+a1)+(a2+a3) + uu, 0.f);
        }
    }

    float w2[DD];
#pragma unroll
    for (int e = 0; e < DD; e++) w2[e] = g_W2s[e*DD + tid];
    float t2 = g_t2l[tid];
    __syncthreads();

    float m[2];
#pragma unroll
    for (int q = 0; q < 2; q++) {
        const float4* h4p = (const float4*)hs[q];
        float mm = -FLT_MAX;
        for (int k = 0; k < KK; k++) {
            float a0=0.f,a1=0.f,a2=0.f,a3=0.f;
#pragma unroll
            for (int e4 = 0; e4 < 32; e4++) {
                float4 h4 = h4p[k*32 + e4];
                a0 = fmaf(h4.x, w2[e4*4+0], a0);
                a1 = fmaf(h4.y, w2[e4*4+1], a1);
                a2 = fmaf(h4.z, w2[e4*4+2], a2);
                a3 = fmaf(h4.w, w2[e4*4+3], a3);
            }
            float acc = (a0+a1)+(a2+a3);
            mm = fmaxf(mm, acc);
        }
        m[q] = fmaxf(mm + t2, 0.f);    // max-then-(+t2,relu): monotone, identical result
    }
    size_t off = (size_t)b*(DD*SS) + (size_t)tid*SS + s0;
    float2 v; v.x = m[0]; v.y = m[1];
    *(float2*)(out + OFF_F1 + off) = v;
    *(float2*)(out + OFF_F2 + off) = v;
}

// ---------------- launch ----------------
extern "C" void kernel_launch(void* const* d_in, const int* in_sizes, int n_in,
                              void* d_out, int out_size)
{
    const float* x   = (const float*)d_in[0];
    const float* c1w = (const float*)d_in[1];
    const float* c2w = (const float*)d_in[2];
    const float* l1w = (const float*)d_in[3];
    const float* l2w = (const float*)d_in[4];
    const float* b1g = (const float*)d_in[5],  *b1b = (const float*)d_in[6],
               * b1m = (const float*)d_in[7],  *b1v = (const float*)d_in[8];
    const float* b2g = (const float*)d_in[9],  *b2b = (const float*)d_in[10],
               * b2m = (const float*)d_in[11], *b2v = (const float*)d_in[12];
    const float* g1g = (const float*)d_in[13], *g1b = (const float*)d_in[14],
               * g1m = (const float*)d_in[15], *g1v = (const float*)d_in[16];
    const float* g2g = (const float*)d_in[17], *g2b = (const float*)d_in[18],
               * g2m = (const float*)d_in[19], *g2v = (const float*)d_in[20];
    float* out = (float*)d_out;

    prep_kernel<<<64, 256>>>(c1w, c2w, l1w, l2w,
                             b1g, b1b, b1m, b1v, b2g, b2b, b2m, b2v,
                             g1g, g1b, g1m, g1v, g2g, g2b, g2m, g2v);
    fps_feat_kernel<<<BB + BB*NN/1024, 1024>>>(x, out);      // 8 fps + 64 feat blocks
    knn_u_kernel<<<BB*SS/KNN_WPB + 64, 256>>>(x);            // 1024 knn + 64 u blocks
    l1l2_kernel<<<BB*SS/2, 128>>>(out);
}

// round 16
// speedup vs baseline: 1.1993x; 1.0689x over previous
#include <cuda_runtime.h>
#include <cstdint>
#include <cfloat>

#define BB 8
#define NN 8192
#define SS 1024
#define KK 32
#define CC 64
#define DD 128
#define EPSF 1e-5f

// output layout: new_xyz (8,1024,3), feature (8,128,1024), new_xyz, feature
#define OFF_F1  24576
#define OFF_NX2 1073152
#define OFF_F2  1097728

// mega-kernel block ranges (512 threads each)
#define FPS_B0   0
#define FEAT_B0  8             // 128 feat blocks
#define KNN_B0   136           // 512 knn blocks, 16 warp-queries each
#define TOT_BLKS 648

// ---------------- scratch (device globals; no allocation) ----------------
__device__ float g_f[BB*NN*CC];                 // 16 MB: per-point features
__device__ int   g_fps[BB*SS];
__device__ int   g_knn[BB*SS*KK];
__device__ int   g_prog[BB*32];                 // fps progress, 128B-padded per batch
// prepped (bn-folded) weights
__device__ float g_c1s[CC*3], g_t1[CC];
__device__ float g_c2s[CC*CC], g_t2c[CC];
__device__ float g_W1s[CC*DD];   // [d][o] = lconv1_w[o][d]      * s1l[o]
__device__ float g_Wd [CC*DD];   // [d][o] = (W[o][64+d]-W[o][d])* s1l[o]
__device__ float g_t1l[DD];
__device__ float g_W2s[DD*DD];   // [e][o] = lconv2_w[o][e] * s2l[o]
__device__ float g_t2l[DD];

// ---------------- packed f32x2 helpers (per-lane rn == scalar rn) ----------------
__device__ __forceinline__ unsigned long long pk2(float a, float b) {
    unsigned long long r; asm("mov.b64 %0, {%1,%2};" : "=l"(r) : "f"(a), "f"(b)); return r;
}
__device__ __forceinline__ void upk2(unsigned long long v, float& a, float& b) {
    asm("mov.b64 {%0,%1}, %2;" : "=f"(a), "=f"(b) : "l"(v));
}
__device__ __forceinline__ unsigned long long add2(unsigned long long a, unsigned long long b) {
    unsigned long long r; asm("add.rn.f32x2 %0, %1, %2;" : "=l"(r) : "l"(a), "l"(b)); return r;
}
__device__ __forceinline__ unsigned long long mul2(unsigned long long a, unsigned long long b) {
    unsigned long long r; asm("mul.rn.f32x2 %0, %1, %2;" : "=l"(r) : "l"(a), "l"(b)); return r;
}
__device__ __forceinline__ void st_release(int* p, int v) {
    asm volatile("st.release.gpu.b32 [%0], %1;" :: "l"(p), "r"(v) : "memory");
}
__device__ __forceinline__ int ld_acquire(const int* p) {
    int v; asm volatile("ld.acquire.gpu.b32 %0, [%1];" : "=r"(v) : "l"(p) : "memory"); return v;
}

// ---------------- prep: fold BN into weights + reset sync state ----------------
__global__ void prep_kernel(
    const float* __restrict__ c1w, const float* __restrict__ c2w,
    const float* __restrict__ l1w, const float* __restrict__ l2w,
    const float* __restrict__ b1g, const float* __restrict__ b1b, const float* __restrict__ b1m, const float* __restrict__ b1v,
    const float* __restrict__ b2g, const float* __restrict__ b2b, const float* __restrict__ b2m, const float* __restrict__ b2v,
    const float* __restrict__ g1g, const float* __restrict__ g1b, const float* __restrict__ g1m, const float* __restrict__ g1v,
    const float* __restrict__ g2g, const float* __restrict__ g2b, const float* __restrict__ g2m, const float* __restrict__ g2v)
{
    int t = blockIdx.x * blockDim.x + threadIdx.x;
    int st = gridDim.x * blockDim.x;
    if (t < BB*32) g_prog[t] = 0;
    for (int i = t; i < CC*3; i += st) { int e = i/3; float s = b1g[e]*rsqrtf(b1v[e]+EPSF); g_c1s[i] = c1w[i]*s; }
    for (int e = t; e < CC; e += st)  { float s = b1g[e]*rsqrtf(b1v[e]+EPSF); g_t1[e] = b1b[e]-b1m[e]*s; }
    for (int i = t; i < CC*CC; i += st){ int f = i/CC; float s = b2g[f]*rsqrtf(b2v[f]+EPSF); g_c2s[i] = c2w[i]*s; }
    for (int f = t; f < CC; f += st)  { float s = b2g[f]*rsqrtf(b2v[f]+EPSF); g_t2c[f] = b2b[f]-b2m[f]*s; }
    for (int i = t; i < CC*DD; i += st){
        int d = i / DD, o = i % DD;
        float s = g1g[o]*rsqrtf(g1v[o]+EPSF);
        g_W1s[i] = l1w[o*DD + d]*s;
        g_Wd [i] = (l1w[o*DD + CC + d] - l1w[o*DD + d])*s;
    }
    for (int o = t; o < DD; o += st) { float s = g1g[o]*rsqrtf(g1v[o]+EPSF); g_t1l[o] = g1b[o]-g1m[o]*s; }
    for (int i = t; i < DD*DD; i += st){
        int e = i / DD, o = i % DD;
        float s = g2g[o]*rsqrtf(g2v[o]+EPSF);
        g_W2s[i] = l2w[o*DD + e]*s;
    }
    for (int o = t; o < DD; o += st) { float s = g2g[o]*rsqrtf(g2v[o]+EPSF); g_t2l[o] = g2b[o]-g2m[o]*s; }
}

// ---------------- MEGA: fps(0..7) + feat(8..135) + knn(136..647, spin on coarse progress) ----------------
__global__ void __launch_bounds__(512) mega_kernel(const float* __restrict__ x, float* __restrict__ out)
{
    int tid = threadIdx.x;
    int bid = blockIdx.x;

    if (bid < FEAT_B0) {
        // ---------------- FPS path (R11/R14 512-thread version, coarse publish) ----------------
        __shared__ unsigned int pd[2][16];
        __shared__ unsigned int pi[2][16];
        int b = bid;
        int lane = tid & 31, wid = tid >> 5;
        const float* xb = x + (size_t)b * NN * 3;

        float rd[16];
        unsigned long long rx2[8], ry2[8], rz2[8];
#pragma unroll
        for (int jp = 0; jp < 8; jp++) {
            int i0 = tid + (2*jp)*512, i1 = i0 + 512;
            float ax = xb[i0*3], ay = xb[i0*3+1], az = xb[i0*3+2];
            float bx_ = xb[i1*3], by_ = xb[i1*3+1], bz_ = xb[i1*3+2];
            rx2[jp] = pk2(ax, bx_); ry2[jp] = pk2(ay, by_); rz2[jp] = pk2(az, bz_);
            rd[2*jp] = 1e10f; rd[2*jp+1] = 1e10f;
        }
        float cx = __ldg(xb), cy = __ldg(xb+1), cz = __ldg(xb+2);
        int far = 0;

        for (int t = 0; t < SS; t++) {
            if (tid == 0) {
                g_fps[b*SS + t] = far;
                int o1 = (b*SS + t) * 3;
                out[o1] = cx; out[o1+1] = cy; out[o1+2] = cz;
                out[OFF_NX2+o1] = cx; out[OFF_NX2+o1+1] = cy; out[OFF_NX2+o1+2] = cz;
                if ((t & 15) == 15) st_release(&g_prog[b*32], t + 1);   // coarse publish
            }
            unsigned long long nx = pk2(-cx, -cx), ny = pk2(-cy, -cy), nz = pk2(-cz, -cz);
            // per lane: fadd(fadd(fmul(dx,dx),fmul(dy,dy)),fmul(dz,dz)) in rn — reference rounding
#pragma unroll
            for (int jp = 0; jp < 8; jp++) {
                unsigned long long dx = add2(rx2[jp], nx);
                unsigned long long dy = add2(ry2[jp], ny);
                unsigned long long dz = add2(rz2[jp], nz);
                unsigned long long s  = add2(add2(mul2(dx,dx), mul2(dy,dy)), mul2(dz,dz));
                float s0, s1; upk2(s, s0, s1);
                rd[2*jp]   = fminf(rd[2*jp],   s0);
                rd[2*jp+1] = fminf(rd[2*jp+1], s1);
            }
            // thread-local argmax: max value, then FIRST j (ascending j == ascending global idx)
            float m = rd[0];
#pragma unroll
            for (int j = 1; j < 16; j++) m = fmaxf(m, rd[j]);
            int j0 = 15;
#pragma unroll
            for (int j = 14; j >= 0; j--) if (rd[j] == m) j0 = j;
            unsigned int mb  = __float_as_uint(m);
            unsigned int inv = (unsigned)(NN-1 - (tid + j0*512));
            unsigned int wmax = __reduce_max_sync(0xffffffffu, mb);
            unsigned int winv = __reduce_max_sync(0xffffffffu, (mb == wmax) ? inv : 0u);
            if (lane == 0) { pd[t & 1][wid] = wmax; pi[t & 1][wid] = winv; }
            __syncthreads();
            unsigned int d2 = pd[t & 1][lane & 15];
            unsigned int i2 = pi[t & 1][lane & 15];
            unsigned int gmax = __reduce_max_sync(0xffffffffu, d2);
            unsigned int ginv = __reduce_max_sync(0xffffffffu, (d2 == gmax) ? i2 : 0u);
            far = NN-1 - (int)ginv;
            cx = __ldg(xb + far*3); cy = __ldg(xb + far*3 + 1); cz = __ldg(xb + far*3 + 2);
        }
    } else if (bid < KNN_B0) {
        // ---------------- feat path ----------------
        __shared__ float sc1[CC*3], st1[CC], st2[CC];
        __shared__ float4 sc2[CC*16];
        for (int i = tid; i < CC*3; i += 512) sc1[i] = g_c1s[i];
        for (int i = tid; i < CC; i += 512) { st1[i] = g_t1[i]; st2[i] = g_t2c[i]; }
        for (int i = tid; i < CC*16; i += 512) sc2[i] = ((const float4*)g_c2s)[i];
        __syncthreads();

        int p = (bid - FEAT_B0) * 512 + tid;              // 0..65535
        float x0 = x[p*3], x1 = x[p*3+1], x2 = x[p*3+2];
        float h[CC];
#pragma unroll
        for (int e = 0; e < CC; e++)
            h[e] = fmaxf(fmaf(x2, sc1[e*3+2], fmaf(x1, sc1[e*3+1], x0*sc1[e*3])) + st1[e], 0.f);

        float* outf = g_f + (size_t)p * CC;
        for (int o = 0; o < CC; o++) {
            float a0=0.f, a1=0.f, a2=0.f, a3=0.f;
#pragma unroll
            for (int e4 = 0; e4 < 16; e4++) {
                float4 w = sc2[o*16 + e4];
                a0 = fmaf(h[e4*4+0], w.x, a0);
                a1 = fmaf(h[e4*4+1], w.y, a1);
                a2 = fmaf(h[e4*4+2], w.z, a2);
                a3 = fmaf(h[e4*4+3], w.w, a3);
            }
            outf[o] = fmaxf((a0+a1)+(a2+a3) + st2[o], 0.f);
        }
    } else {
        // ---------------- KNN path: 16 warp-queries; spin on coarse fps progress ----------------
        __shared__ float px[512], py[512], pz[512];
        __shared__ int sready;
        int lane = tid & 31, wid = tid >> 5;
        int qb = (bid - KNN_B0) * 16;          // first query (multiple of 16)
        int b = qb >> 10;
        int need = (qb & 1023) + 16;           // a published multiple of 16
        if (tid == 0) {
            while (ld_acquire(&g_prog[b*32]) < need) __nanosleep(256);
            sready = 1;
        }
        __syncthreads();
        (void)sready;

        int sg = qb + wid;
        const float* xb = x + (size_t)b * NN * 3;
        int nq = g_fps[sg];
        float qx = xb[nq*3], qy = xb[nq*3+1], qz = xb[nq*3+2];

        unsigned long long cur = 0xFFFFFFFFFFFFFFFFull;
        unsigned long long worst = 0xFFFFFFFFFFFFFFFFull;

        for (int base = 0; base < NN; base += 512) {
            __syncthreads();
            {
                int n = base + tid;
                px[tid] = xb[n*3]; py[tid] = xb[n*3+1]; pz[tid] = xb[n*3+2];
            }
            __syncthreads();
#pragma unroll 4
            for (int s = 0; s < 512; s += 32) {
                int i = s + lane;
                float dx = qx - px[i], dy = qy - py[i], dz = qz - pz[i];
                float d = fmaf(dz, dz, fmaf(dy, dy, dx*dx));
                unsigned long long cand =
                    ((unsigned long long)__float_as_uint(d) << 32) | (unsigned)(base + i);
                unsigned int ball = __ballot_sync(0xffffffffu, cand < worst);
                while (ball) {                  // warp-uniform loop
                    int src = __ffs(ball) - 1; ball &= ball - 1;
                    unsigned long long ck = __shfl_sync(0xffffffffu, cand, src);
                    if (ck < worst) {
                        unsigned int lt = __ballot_sync(0xffffffffu, cur < ck);
                        int pos = __popc(lt);
                        unsigned long long up = __shfl_up_sync(0xffffffffu, cur, 1);
                        if (lane > pos) cur = up;
                        if (lane == pos) cur = ck;
                        worst = __shfl_sync(0xffffffffu, cur, 31);
                    }
                }
            }
        }
        g_knn[(size_t)sg*KK + lane] = (int)(unsigned)(cur & 0xffffffffu);
    }
}

// ---------------- K3: l1l2 with inline u ----------------
__global__ void __launch_bounds__(128) l1l2_kernel(float* __restrict__ out)
{
    __shared__ float4 gs[KK*16];        // 8 KB: grouped rows of one query
    __shared__ float  hs[2][KK*DD];     // 32 KB: layer-1 activations, 2 queries
    __shared__ float  sc[2][CC];        // centroid features
    __shared__ int    kn[2*KK];
    int tid = threadIdx.x;
    int sg0 = blockIdx.x * 2;
    int b = sg0 >> 10, s0 = sg0 & (SS-1);

    if (tid < 2*KK) kn[tid] = g_knn[(size_t)sg0*KK + tid];
    if (tid < 2*CC) {
        int q = tid >> 6, d = tid & 63;
        sc[q][d] = g_f[((size_t)(b*NN) + g_fps[sg0 + q])*CC + d];
    }
    __syncthreads();

    // inline u: identical accumulator split/order as the old u_kernel; Wd shared across q
    float uu[2];
    {
        float a00=0.f,a01=0.f,a02=0.f,a03=0.f;
        float a10=0.f,a11=0.f,a12=0.f,a13=0.f;
#pragma unroll 4
        for (int d = 0; d < CC; d += 4) {
            float w0 = g_Wd[(d+0)*DD + tid];
            float w1_ = g_Wd[(d+1)*DD + tid];
            float w2_ = g_Wd[(d+2)*DD + tid];
            float w3 = g_Wd[(d+3)*DD + tid];
            a00 = fmaf(sc[0][d+0], w0, a00);  a10 = fmaf(sc[1][d+0], w0, a10);
            a01 = fmaf(sc[0][d+1], w1_, a01); a11 = fmaf(sc[1][d+1], w1_, a11);
            a02 = fmaf(sc[0][d+2], w2_, a02); a12 = fmaf(sc[1][d+2], w2_, a12);
            a03 = fmaf(sc[0][d+3], w3, a03);  a13 = fmaf(sc[1][d+3], w3, a13);
        }
        float t1l = g_t1l[tid];
        uu[0] = (a00+a01)+(a02+a03) + t1l;
        uu[1] = (a10+a11)+(a12+a13) + t1l;
    }

    float w1[CC];
#pragma unroll
    for (int d = 0; d < CC; d++) w1[d] = g_W1s[d*DD + tid];

    for (int q = 0; q < 2; q++) {
        __syncthreads();
#pragma unroll
        for (int j = 0; j < 4; j++) {
            int idx = tid + j*128;
            int r = idx >> 4, c = idx & 15;
            int n = kn[q*KK + r];
            gs[idx] = ((const float4*)(g_f + ((size_t)(b*NN) + n)*CC))[c];
        }
        __syncthreads();
        for (int k = 0; k < KK; k++) {
            float a0=0.f,a1=0.f,a2=0.f,a3=0.f;
#pragma unroll
            for (int d4 = 0; d4 < 16; d4++) {
                float4 g4 = gs[k*16 + d4];
                a0 = fmaf(g4.x, w1[d4*4+0], a0);
                a1 = fmaf(g4.y, w1[d4*4+1], a1);
                a2 = fmaf(g4.z, w1[d4*4+2], a2);
                a3 = fmaf(g4.w, w1[d4*4+3], a3);
            }
            hs[q][k*DD + tid] = fmaxf((a0+a1)+(a2+a3) + uu[q], 0.f);
        }
    }

    float w2[DD];
#pragma unroll
    for (int e = 0; e < DD; e++) w2[e] = g_W2s[e*DD + tid];
    float t2 = g_t2l[tid];
    __syncthreads();

    float m[2];
#pragma unroll
    for (int q = 0; q < 2; q++) {
        const float4* h4p = (const float4*)hs[q];
        float mm = -FLT_MAX;
        for (int k = 0; k < KK; k++) {
            float a0=0.f,a1=0.f,a2=0.f,a3=0.f;
#pragma unroll
            for (int e4 = 0; e4 < 32; e4++) {
                float4 h4 = h4p[k*32 + e4];
                a0 = fmaf(h4.x, w2[e4*4+0], a0);
                a1 = fmaf(h4.y, w2[e4*4+1], a1);
                a2 = fmaf(h4.z, w2[e4*4+2], a2);
                a3 = fmaf(h4.w, w2[e4*4+3], a3);
            }
            float acc = (a0+a1)+(a2+a3);
            mm = fmaxf(mm, acc);
        }
        m[q] = fmaxf(mm + t2, 0.f);    // max-then-(+t2,relu): monotone, identical result
    }
    size_t off = (size_t)b*(DD*SS) + (size_t)tid*SS + s0;
    float2 v; v.x = m[0]; v.y = m[1];
    *(float2*)(out + OFF_F1 + off) = v;
    *(float2*)(out + OFF_F2 + off) = v;
}

// ---------------- launch ----------------
extern "C" void kernel_launch(void* const* d_in, const int* in_sizes, int n_in,
                              void* d_out, int out_size)
{
    const float* x   = (const float*)d_in[0];
    const float* c1w = (const float*)d_in[1];
    const float* c2w = (const float*)d_in[2];
    const float* l1w = (const float*)d_in[3];
    const float* l2w = (const float*)d_in[4];
    const float* b1g = (const float*)d_in[5],  *b1b = (const float*)d_in[6],
               * b1m = (const float*)d_in[7],  *b1v = (const float*)d_in[8];
    const float* b2g = (const float*)d_in[9],  *b2b = (const float*)d_in[10],
               * b2m = (const float*)d_in[11], *b2v = (const float*)d_in[12];
    const float* g1g = (const float*)d_in[13], *g1b = (const float*)d_in[14],
               * g1m = (const float*)d_in[15], *g1v = (const float*)d_in[16];
    const float* g2g = (const float*)d_in[17], *g2b = (const float*)d_in[18],
               * g2m = (const float*)d_in[19], *g2v = (const float*)d_in[20];
    float* out = (float*)d_out;

    prep_kernel<<<64, 256>>>(c1w, c2w, l1w, l2w,
                             b1g, b1b, b1m, b1v, b2g, b2b, b2m, b2v,
                             g1g, g1b, g1m, g1v, g2g, g2b, g2m, g2v);
    mega_kernel<<<TOT_BLKS, 512>>>(x, out);
    l1l2_kernel<<<BB*SS/2, 128>>>(out);
}